// round 8
// baseline (speedup 1.0000x reference)
#include <cuda_runtime.h>
#include <cstdint>
#include <math.h>

#define BVAL 16
#define HVAL 256
#define NODES0 65536

// ---------------- device scratch ----------------
__device__ __align__(16) float g_bufA_h[(size_t)NODES0 * HVAL];
__device__ __align__(16) float g_bufA_c[(size_t)NODES0 * HVAL];
__device__ __align__(16) float g_bufB_h[(size_t)(NODES0 / 2) * HVAL];
__device__ __align__(16) float g_bufB_c[(size_t)(NODES0 / 2) * HVAL];
// g_Wk flat [k(512)][p(1280)]; p = grp*320 + cb*80 + g*16 + j16, channel = grp*64+cb*16+j16
__device__ __align__(16) float g_Wk[(size_t)512 * 1280];
__device__ __align__(16) float g_WpK[(size_t)256 * 256];    // W_proj [k][n], tf32-RN
__device__ __align__(16) float g_bt[1280];                  // biases in same p order

__device__ unsigned g_bar_cnt = 0;
__device__ unsigned g_bar_gen = 0;

// ---------------- helpers ----------------
__device__ __forceinline__ float rnd_tf32(float x) {
    uint32_t r;
    asm("cvt.rna.tf32.f32 %0, %1;" : "=r"(r) : "f"(x));
    return __uint_as_float(r);
}
__device__ __forceinline__ float sigm(float x) { return 1.0f / (1.0f + __expf(-x)); }

__device__ __forceinline__ void cp16(void* dst, const float* src) {
    uint32_t d = (uint32_t)__cvta_generic_to_shared(dst);
    asm volatile("cp.async.cg.shared.global [%0], [%1], 16;"
                 :: "r"(d), "l"(__cvta_generic_to_global(src)));
}
#define CP_COMMIT() asm volatile("cp.async.commit_group;" ::: "memory")
#define CP_WAIT2()  asm volatile("cp.async.wait_group 2;" ::: "memory")
#define CP_WAIT1()  asm volatile("cp.async.wait_group 1;" ::: "memory")
#define CP_WAIT0()  asm volatile("cp.async.wait_group 0;" ::: "memory")

__device__ __forceinline__ void mma_tf32(float* c, const uint32_t* a, uint32_t b0, uint32_t b1) {
    asm volatile("mma.sync.aligned.m16n8k8.row.col.f32.tf32.tf32.f32 "
                 "{%0,%1,%2,%3}, {%4,%5,%6,%7}, {%8,%9}, {%0,%1,%2,%3};"
                 : "+f"(c[0]), "+f"(c[1]), "+f"(c[2]), "+f"(c[3])
                 : "r"(a[0]), "r"(a[1]), "r"(a[2]), "r"(a[3]), "r"(b0), "r"(b1));
}

// ---------------- pack kernel ----------------
__global__ void pack_weights(const float* __restrict__ Wp,
                             const float* __restrict__ Wfl, const float* __restrict__ Wfr,
                             const float* __restrict__ Wi,  const float* __restrict__ Wo,
                             const float* __restrict__ Wc,
                             const float* __restrict__ bfl, const float* __restrict__ bfr,
                             const float* __restrict__ bi,  const float* __restrict__ bo,
                             const float* __restrict__ bc) {
    int idx = blockIdx.x * blockDim.x + threadIdx.x;
    int stride = gridDim.x * blockDim.x;
    for (int i = idx; i < 512 * 1280; i += stride) {
        int k = i / 1280, p = i - k * 1280;
        int grp = p / 320, r = p - grp * 320;
        int cb = r / 80, r2 = r - cb * 80;
        int g5 = r2 >> 4, j16 = r2 & 15;
        int col = grp * 64 + cb * 16 + j16;
        const float* W = (g5 == 0) ? Wfl : (g5 == 1) ? Wfr : (g5 == 2) ? Wi : (g5 == 3) ? Wo : Wc;
        g_Wk[i] = rnd_tf32(W[k * 256 + col]);
    }
    for (int i = idx; i < 256 * 256; i += stride) g_WpK[i] = rnd_tf32(Wp[i]);
    for (int i = idx; i < 1280; i += stride) {
        int grp = i / 320, r = i - grp * 320;
        int cb = r / 80, r2 = r - cb * 80;
        int g5 = r2 >> 4, j16 = r2 & 15;
        int col = grp * 64 + cb * 16 + j16;
        const float* bb = (g5 == 0) ? bfl : (g5 == 1) ? bfr : (g5 == 2) ? bi : (g5 == 3) ? bo : bc;
        g_bt[i] = bb[col];
    }
}

// ================= LEVEL KERNEL (big levels) =================
// CTA tile 128 x 320 (64 channels x 5 gates), K=512, chunk=32, 3-stage.
// Warps: 2 along M (64 rows) x 4 along N (80 cols). acc[4][10][4].
#define ASTR 36
#define BSTR3 328
#define LV_AF (128 * ASTR)           // 4608 floats
#define LV_BF (32 * BSTR3)           // 10496 floats
#define LV_STGF (LV_AF + LV_BF)      // 15104
#define LV_SMEM (3 * LV_STGF * 4)    // 181248 bytes

__global__ __launch_bounds__(256, 1) void level_fused(const float* __restrict__ Hin,
                                                      const float* __restrict__ Cin,
                                                      float* __restrict__ Hout,
                                                      float* __restrict__ Cout, int Mout) {
    extern __shared__ float dsm[];
    __shared__ float s_bias[320];
    const int tid = threadIdx.x, wid = tid >> 5, lane = tid & 31;
    const int qr = lane >> 2, qc = lane & 3;
    const int wm = wid & 1, wn = wid >> 1;       // 2 M-warps x 4 N-warps
    const int mBase = blockIdx.x * 128;
    const int grp = blockIdx.y;
    const int p0 = grp * 320, c0 = grp * 64;

    for (int i = tid; i < 320; i += 256) s_bias[i] = g_bt[p0 + i];

    float acc[4][10][4];
#pragma unroll
    for (int a = 0; a < 4; a++)
#pragma unroll
        for (int b = 0; b < 10; b++)
#pragma unroll
            for (int e = 0; e < 4; e++) acc[a][b][e] = 0.f;

    auto load_chunk = [&](int kc) {
        float* As = dsm + (kc % 3) * LV_STGF;
        float* Bs = As + LV_AF;
#pragma unroll
        for (int t = 0; t < 4; t++) {
            int v = tid + t * 256;
            int r = v >> 3, c = v & 7;
            int row = mBase + r; if (row >= Mout) row = Mout - 1;
            cp16(As + r * ASTR + c * 4, Hin + (size_t)row * 512 + kc * 32 + c * 4);
        }
#pragma unroll
        for (int t = 0; t < 10; t++) {
            int v = tid + t * 256;
            int kr = v / 80, c4 = v - kr * 80;
            cp16(Bs + kr * BSTR3 + c4 * 4, g_Wk + (size_t)(kc * 32 + kr) * 1280 + p0 + c4 * 4);
        }
        CP_COMMIT();
    };

    load_chunk(0); load_chunk(1); load_chunk(2);
    for (int i = 0; i < 16; i++) {
        CP_WAIT2();
        __syncthreads();
        const float* As = dsm + (i % 3) * LV_STGF;
        const float* Bs = As + LV_AF;
#pragma unroll
        for (int ks = 0; ks < 4; ks++) {
            uint32_t a[4][4];
#pragma unroll
            for (int ma = 0; ma < 4; ma++) {
                const float* ap = As + (wm * 64 + ma * 16 + qr) * ASTR + ks * 8 + qc;
                a[ma][0] = __float_as_uint(ap[0]);
                a[ma][1] = __float_as_uint(ap[8 * ASTR]);
                a[ma][2] = __float_as_uint(ap[4]);
                a[ma][3] = __float_as_uint(ap[8 * ASTR + 4]);
            }
            const float* brow = Bs + (ks * 8 + qc) * BSTR3;
#pragma unroll
            for (int na = 0; na < 10; na++) {
                int col = wn * 80 + (na >> 1) * 16 + (na & 1) * 8 + qr;
                uint32_t b0 = __float_as_uint(brow[col]);
                uint32_t b1 = __float_as_uint(brow[4 * BSTR3 + col]);
#pragma unroll
                for (int ma = 0; ma < 4; ma++) mma_tf32(acc[ma][na], a[ma], b0, b1);
            }
        }
        __syncthreads();
        if (i + 3 < 16) load_chunk(i + 3);
    }

    // fused gate epilogue: warp covers rows wm*64..+63, channels wn*16..+15 (5 gates each)
#pragma unroll
    for (int ma = 0; ma < 4; ma++) {
#pragma unroll
        for (int eh = 0; eh < 2; eh++) {
            int row = mBase + wm * 64 + ma * 16 + qr + eh * 8;
            if (row < Mout) {
#pragma unroll
                for (int h = 0; h < 2; h++) {
                    int ch = wn * 16 + h * 8 + qc * 2;         // local channel (0..63)
                    float2 cl = *(const float2*)(Cin + (size_t)row * 512 + c0 + ch);
                    float2 cr = *(const float2*)(Cin + (size_t)row * 512 + 256 + c0 + ch);
                    float hv[2], cv[2];
#pragma unroll
                    for (int e = 0; e < 2; e++) {
                        int bi_ = wn * 80 + h * 8 + qc * 2 + e;
                        float fl = sigm(acc[ma][0 * 2 + h][eh * 2 + e] + s_bias[bi_ + 0 * 16]);
                        float fr = sigm(acc[ma][1 * 2 + h][eh * 2 + e] + s_bias[bi_ + 1 * 16]);
                        float ig = sigm(acc[ma][2 * 2 + h][eh * 2 + e] + s_bias[bi_ + 2 * 16]);
                        float og = sigm(acc[ma][3 * 2 + h][eh * 2 + e] + s_bias[bi_ + 3 * 16]);
                        float cc = tanhf(acc[ma][4 * 2 + h][eh * 2 + e] + s_bias[bi_ + 4 * 16]);
                        float clv = (e == 0) ? cl.x : cl.y;
                        float crv = (e == 0) ? cr.x : cr.y;
                        float cn = fl * clv + fr * crv + ig * cc;
                        cv[e] = cn;
                        hv[e] = rnd_tf32(og * tanhf(cn));
                    }
                    *(float2*)(Hout + (size_t)row * 256 + c0 + ch) = make_float2(hv[0], hv[1]);
                    *(float2*)(Cout + (size_t)row * 256 + c0 + ch) = make_float2(cv[0], cv[1]);
                }
            }
        }
    }
}

// ================= LEAF KERNEL (2 CTA/SM, direct emb + in-reg tf32 round) =================
#define BSTRL 136
#define LF_AF (128 * ASTR)          // 4608
#define LF_BF (32 * BSTRL)          // 4352
#define LF_STGF (LF_AF + LF_BF)     // 8960
#define LF_SMEM (2 * LF_STGF * 4)   // 71680

__global__ __launch_bounds__(256, 2) void leaf_fused(const int* __restrict__ ids,
                                                     const float* __restrict__ emb,
                                                     const float* __restrict__ bp,
                                                     float* __restrict__ Hout,
                                                     float* __restrict__ Cout) {
    extern __shared__ float dsm[];
    __shared__ int s_ids[128];
    __shared__ float s_bp[128];
    const int tid = threadIdx.x, wid = tid >> 5, lane = tid & 31;
    const int qr = lane >> 2, qc = lane & 3;
    const int wm = wid >> 1, wn = wid & 1;
    const int mBase = blockIdx.x * 128;
    const int nBase = blockIdx.y * 128;

    if (tid < 128) {
        s_ids[tid] = ids[mBase + tid];
        s_bp[tid] = bp[nBase + tid];
    }
    __syncthreads();

    float acc[2][8][4];
#pragma unroll
    for (int a = 0; a < 2; a++)
#pragma unroll
        for (int b = 0; b < 8; b++)
#pragma unroll
            for (int e = 0; e < 4; e++) acc[a][b][e] = 0.f;

    auto load_chunk = [&](int kc) {
        float* As = dsm + (kc & 1) * LF_STGF;
        float* Bs = As + LF_AF;
#pragma unroll
        for (int t = 0; t < 4; t++) {
            int v = tid + t * 256;
            int r = v >> 3, c = v & 7;
            cp16(As + r * ASTR + c * 4, emb + (size_t)s_ids[r] * 256 + kc * 32 + c * 4);
        }
#pragma unroll
        for (int t = 0; t < 4; t++) {
            int v = tid + t * 256;
            int kr = v >> 5, c4 = v & 31;
            cp16(Bs + kr * BSTRL + c4 * 4, g_WpK + (size_t)(kc * 32 + kr) * 256 + nBase + c4 * 4);
        }
        CP_COMMIT();
    };

    load_chunk(0);
    for (int i = 0; i < 8; i++) {
        if (i + 1 < 8) { load_chunk(i + 1); CP_WAIT1(); } else { CP_WAIT0(); }
        __syncthreads();
        const float* As = dsm + (i & 1) * LF_STGF;
        const float* Bs = As + LF_AF;
#pragma unroll
        for (int ks = 0; ks < 4; ks++) {
            uint32_t a[2][4];
#pragma unroll
            for (int ma = 0; ma < 2; ma++) {
                const float* ap = As + (wm * 32 + ma * 16 + qr) * ASTR + ks * 8 + qc;
                a[ma][0] = __float_as_uint(rnd_tf32(ap[0]));
                a[ma][1] = __float_as_uint(rnd_tf32(ap[8 * ASTR]));
                a[ma][2] = __float_as_uint(rnd_tf32(ap[4]));
                a[ma][3] = __float_as_uint(rnd_tf32(ap[8 * ASTR + 4]));
            }
            const float* brow = Bs + (ks * 8 + qc) * BSTRL;
#pragma unroll
            for (int na = 0; na < 8; na++) {
                int col = wn * 64 + na * 8 + qr;
                uint32_t b0 = __float_as_uint(brow[col]);
                uint32_t b1 = __float_as_uint(brow[4 * BSTRL + col]);
                mma_tf32(acc[0][na], a[0], b0, b1);
                mma_tf32(acc[1][na], a[1], b0, b1);
            }
        }
        __syncthreads();
    }

#pragma unroll
    for (int ma = 0; ma < 2; ma++) {
#pragma unroll
        for (int eh = 0; eh < 2; eh++) {
            int row = mBase + wm * 32 + ma * 16 + qr + eh * 8;
#pragma unroll
            for (int na = 0; na < 8; na++) {
                int cl = wn * 64 + na * 8 + qc * 2;
                float h0 = acc[ma][na][eh * 2 + 0] + s_bp[cl + 0];
                float h1 = acc[ma][na][eh * 2 + 1] + s_bp[cl + 1];
                *(float2*)(Hout + (size_t)row * 256 + nBase + cl) =
                    make_float2(rnd_tf32(h0), rnd_tf32(h1));
                *(float2*)(Cout + (size_t)row * 256 + nBase + cl) =
                    make_float2(tanhf(h0), tanhf(h1));
            }
        }
    }
}

// ================= PERSISTENT SMALL-LEVELS KERNEL =================
// Tile 64 x 320, warps 2M(32) x 4N(80). 3-stage. Same p-order as level_fused.
#define SL_GRID 128
#define SL_AF (64 * ASTR)            // 2304
#define SL_BF (32 * BSTR3)           // 10496
#define SL_STGF (SL_AF + SL_BF)      // 12800
#define SL_SMEM (3 * SL_STGF * 4)    // 153600

__global__ __launch_bounds__(256, 1) void small_levels(float* __restrict__ inH0,
                                                       float* __restrict__ inC0,
                                                       float* __restrict__ outH0,
                                                       float* __restrict__ outC0,
                                                       const float* __restrict__ Wcls,
                                                       const float* __restrict__ bcls,
                                                       float* __restrict__ out) {
    extern __shared__ float dsm[];
    __shared__ float s_bias[320];
    const int tid = threadIdx.x, wid = tid >> 5, lane = tid & 31;
    const int qr = lane >> 2, qc = lane & 3;
    const int wm = wid & 1, wn = wid >> 1;

    unsigned gen = 0;
    if (tid == 0) gen = *(volatile unsigned*)&g_bar_gen;

    float* inH = inH0;  float* inC = inC0;
    float* outH = outH0; float* outC = outC0;

    int cur = 4096;
    while (cur > 16) {
        const int Mout = cur >> 1;
        const int mtiles = (Mout + 63) >> 6;
        const int nt = mtiles * 4;
        for (int t = blockIdx.x; t < nt; t += SL_GRID) {
            const int grp = t / mtiles;
            const int mtile = t - grp * mtiles;
            const int p0 = grp * 320, c0 = grp * 64;
            const int mBase = mtile * 64;

            for (int i = tid; i < 320; i += 256) s_bias[i] = g_bt[p0 + i];

            float acc[2][10][4];
#pragma unroll
            for (int a = 0; a < 2; a++)
#pragma unroll
                for (int b = 0; b < 10; b++)
#pragma unroll
                    for (int e = 0; e < 4; e++) acc[a][b][e] = 0.f;

            auto load_chunk = [&](int kc) {
                float* As = dsm + (kc % 3) * SL_STGF;
                float* Bs = As + SL_AF;
#pragma unroll
                for (int tt = 0; tt < 2; tt++) {
                    int v = tid + tt * 256;
                    int r = v >> 3, c = v & 7;
                    int row = mBase + r; if (row >= Mout) row = Mout - 1;
                    cp16(As + r * ASTR + c * 4, inH + (size_t)row * 512 + kc * 32 + c * 4);
                }
#pragma unroll
                for (int tt = 0; tt < 10; tt++) {
                    int v = tid + tt * 256;
                    int kr = v / 80, c4 = v - kr * 80;
                    cp16(Bs + kr * BSTR3 + c4 * 4, g_Wk + (size_t)(kc * 32 + kr) * 1280 + p0 + c4 * 4);
                }
                CP_COMMIT();
            };

            load_chunk(0); load_chunk(1); load_chunk(2);
            for (int i = 0; i < 16; i++) {
                CP_WAIT2();
                __syncthreads();
                const float* As = dsm + (i % 3) * SL_STGF;
                const float* Bs = As + SL_AF;
#pragma unroll
                for (int ks = 0; ks < 4; ks++) {
                    uint32_t a[2][4];
#pragma unroll
                    for (int ma = 0; ma < 2; ma++) {
                        const float* ap = As + (wm * 32 + ma * 16 + qr) * ASTR + ks * 8 + qc;
                        a[ma][0] = __float_as_uint(ap[0]);
                        a[ma][1] = __float_as_uint(ap[8 * ASTR]);
                        a[ma][2] = __float_as_uint(ap[4]);
                        a[ma][3] = __float_as_uint(ap[8 * ASTR + 4]);
                    }
                    const float* brow = Bs + (ks * 8 + qc) * BSTR3;
#pragma unroll
                    for (int na = 0; na < 10; na++) {
                        int col = wn * 80 + (na >> 1) * 16 + (na & 1) * 8 + qr;
                        uint32_t b0 = __float_as_uint(brow[col]);
                        uint32_t b1 = __float_as_uint(brow[4 * BSTR3 + col]);
                        mma_tf32(acc[0][na], a[0], b0, b1);
                        mma_tf32(acc[1][na], a[1], b0, b1);
                    }
                }
                __syncthreads();
                if (i + 3 < 16) load_chunk(i + 3);
            }

#pragma unroll
            for (int ma = 0; ma < 2; ma++) {
#pragma unroll
                for (int eh = 0; eh < 2; eh++) {
                    int row = mBase + wm * 32 + ma * 16 + qr + eh * 8;
                    if (row < Mout) {
#pragma unroll
                        for (int h = 0; h < 2; h++) {
                            int ch = wn * 16 + h * 8 + qc * 2;
                            float2 cl = *(const float2*)(inC + (size_t)row * 512 + c0 + ch);
                            float2 cr = *(const float2*)(inC + (size_t)row * 512 + 256 + c0 + ch);
                            float hv[2], cv[2];
#pragma unroll
                            for (int e = 0; e < 2; e++) {
                                int bi_ = wn * 80 + h * 8 + qc * 2 + e;
                                float fl = sigm(acc[ma][0 * 2 + h][eh * 2 + e] + s_bias[bi_ + 0 * 16]);
                                float fr = sigm(acc[ma][1 * 2 + h][eh * 2 + e] + s_bias[bi_ + 1 * 16]);
                                float ig = sigm(acc[ma][2 * 2 + h][eh * 2 + e] + s_bias[bi_ + 2 * 16]);
                                float og = sigm(acc[ma][3 * 2 + h][eh * 2 + e] + s_bias[bi_ + 3 * 16]);
                                float cc = tanhf(acc[ma][4 * 2 + h][eh * 2 + e] + s_bias[bi_ + 4 * 16]);
                                float clv = (e == 0) ? cl.x : cl.y;
                                float crv = (e == 0) ? cr.x : cr.y;
                                float cn = fl * clv + fr * crv + ig * cc;
                                cv[e] = cn;
                                hv[e] = rnd_tf32(og * tanhf(cn));
                            }
                            *(float2*)(outH + (size_t)row * 256 + c0 + ch) = make_float2(hv[0], hv[1]);
                            *(float2*)(outC + (size_t)row * 256 + c0 + ch) = make_float2(cv[0], cv[1]);
                        }
                    }
                }
            }
            __syncthreads();
        }

        // -------- grid-wide barrier --------
        __threadfence();
        __syncthreads();
        if (tid == 0) {
            unsigned arrived = atomicAdd(&g_bar_cnt, 1u);
            if (arrived == SL_GRID - 1) {
                g_bar_cnt = 0;
                __threadfence();
                atomicAdd(&g_bar_gen, 1u);
                gen++;
            } else {
                unsigned cg;
                do {
                    __nanosleep(64);
                    asm volatile("ld.acquire.gpu.u32 %0, [%1];" : "=r"(cg) : "l"(&g_bar_gen) : "memory");
                } while (cg == gen);
                gen = cg;
                __threadfence();
            }
        }
        __syncthreads();

        float* th = inH; inH = outH; outH = th;
        float* tc = inC; inC = outC; outC = tc;
        cur = Mout;
    }

    // classifier on root H — CTA 0
    if (blockIdx.x == 0 && tid < BVAL * 2) {
        int b = tid >> 1, cx = tid & 1;
        float sum = bcls[cx];
        const float* h = inH + (size_t)b * HVAL;
        for (int k = 0; k < HVAL; k++) sum += h[k] * Wcls[k * 2 + cx];
        out[b * 2 + cx] = sum;
    }
}

// ---------------- launch ----------------
extern "C" void kernel_launch(void* const* d_in, const int* in_sizes, int n_in,
                              void* d_out, int out_size) {
    const int*   leaf_ids = (const int*)d_in[0];
    const float* emb  = (const float*)d_in[1];
    const float* Wp   = (const float*)d_in[2];
    const float* bp   = (const float*)d_in[3];
    const float* Wfl  = (const float*)d_in[4];
    const float* bfl  = (const float*)d_in[5];
    const float* Wfr  = (const float*)d_in[6];
    const float* bfr  = (const float*)d_in[7];
    const float* Wi   = (const float*)d_in[8];
    const float* bi   = (const float*)d_in[9];
    const float* Wo   = (const float*)d_in[10];
    const float* bo   = (const float*)d_in[11];
    const float* Wc   = (const float*)d_in[12];
    const float* bc   = (const float*)d_in[13];
    const float* Wcls = (const float*)d_in[14];
    const float* bcls = (const float*)d_in[15];
    float* out = (float*)d_out;

    float *Ah, *Ac, *Bh, *Bc;
    cudaGetSymbolAddress((void**)&Ah, g_bufA_h);
    cudaGetSymbolAddress((void**)&Ac, g_bufA_c);
    cudaGetSymbolAddress((void**)&Bh, g_bufB_h);
    cudaGetSymbolAddress((void**)&Bc, g_bufB_c);

    cudaFuncSetAttribute(level_fused,  cudaFuncAttributeMaxDynamicSharedMemorySize, LV_SMEM);
    cudaFuncSetAttribute(leaf_fused,   cudaFuncAttributeMaxDynamicSharedMemorySize, LF_SMEM);
    cudaFuncSetAttribute(small_levels, cudaFuncAttributeMaxDynamicSharedMemorySize, SL_SMEM);

    pack_weights<<<512, 256>>>(Wp, Wfl, Wfr, Wi, Wo, Wc, bfl, bfr, bi, bo, bc);

    leaf_fused<<<dim3(NODES0 / 128, 2), 256, LF_SMEM>>>(leaf_ids, emb, bp, Ah, Ac);

    float *inH = Ah, *inC = Ac, *outH = Bh, *outC = Bc;
    int cur = NODES0;
    while (cur > 4096) {
        int Mout = cur >> 1;
        dim3 grid(Mout / 128, 4);
        level_fused<<<grid, 256, LV_SMEM>>>(inH, inC, outH, outC, Mout);
        float* t;
        t = inH; inH = outH; outH = t;
        t = inC; inC = outC; outC = t;
        cur = Mout;
    }

    small_levels<<<SL_GRID, 256, SL_SMEM>>>(inH, inC, outH, outC, Wcls, bcls, out);
}

// round 9
// speedup vs baseline: 1.1548x; 1.1548x over previous
#include <cuda_runtime.h>
#include <cstdint>
#include <math.h>

#define BVAL 16
#define HVAL 256
#define NODES0 65536

// ---------------- device scratch ----------------
__device__ __align__(16) float g_bufA_h[(size_t)NODES0 * HVAL];
__device__ __align__(16) float g_bufA_c[(size_t)NODES0 * HVAL];
__device__ __align__(16) float g_bufB_h[(size_t)(NODES0 / 2) * HVAL];
__device__ __align__(16) float g_bufB_c[(size_t)(NODES0 / 2) * HVAL];
// g_Wk n-major: [p(1280)][k(512)], p = grp*160 + gate*32 + jj (channel = grp*32+jj)
__device__ __align__(16) float g_Wk[(size_t)1280 * 512];
// g_WpK n-major: [n(256)][k(256)]
__device__ __align__(16) float g_WpK[(size_t)256 * 256];
__device__ __align__(16) float g_embR[(size_t)50000 * 256]; // emb rounded to tf32-RN
__device__ __align__(16) float g_bt[1280];                  // biases, same p order

__device__ unsigned g_bar_cnt = 0;
__device__ unsigned g_bar_gen = 0;

// ---------------- helpers ----------------
__device__ __forceinline__ float rnd_tf32(float x) {
    uint32_t r;
    asm("cvt.rna.tf32.f32 %0, %1;" : "=r"(r) : "f"(x));
    return __uint_as_float(r);
}
__device__ __forceinline__ float sigm(float x) { return 1.0f / (1.0f + __expf(-x)); }

__device__ __forceinline__ void cp16(void* dst, const float* src) {
    uint32_t d = (uint32_t)__cvta_generic_to_shared(dst);
    asm volatile("cp.async.cg.shared.global [%0], [%1], 16;"
                 :: "r"(d), "l"(__cvta_generic_to_global(src)));
}
#define CP_COMMIT() asm volatile("cp.async.commit_group;" ::: "memory")
#define CP_WAIT1()  asm volatile("cp.async.wait_group 1;" ::: "memory")
#define CP_WAIT0()  asm volatile("cp.async.wait_group 0;" ::: "memory")

__device__ __forceinline__ void mma_tf32(float* c, const uint32_t* a, uint32_t b0, uint32_t b1) {
    asm volatile("mma.sync.aligned.m16n8k8.row.col.f32.tf32.tf32.f32 "
                 "{%0,%1,%2,%3}, {%4,%5,%6,%7}, {%8,%9}, {%0,%1,%2,%3};"
                 : "+f"(c[0]), "+f"(c[1]), "+f"(c[2]), "+f"(c[3])
                 : "r"(a[0]), "r"(a[1]), "r"(a[2]), "r"(a[3]), "r"(b0), "r"(b1));
}

// ldmatrix x4: r0..r3 = four m8n8(b16) matrices = one 16x8 tf32 fragment set
__device__ __forceinline__ void ldsm4(uint32_t* r, const float* p) {
    uint32_t a = (uint32_t)__cvta_generic_to_shared(p);
    asm volatile("ldmatrix.sync.aligned.m8n8.x4.shared.b16 {%0,%1,%2,%3}, [%4];"
                 : "=r"(r[0]), "=r"(r[1]), "=r"(r[2]), "=r"(r[3]) : "r"(a));
}

// ---------------- pack kernel ----------------
__global__ void pack_weights(const float* __restrict__ emb, const float* __restrict__ Wp,
                             const float* __restrict__ Wfl, const float* __restrict__ Wfr,
                             const float* __restrict__ Wi,  const float* __restrict__ Wo,
                             const float* __restrict__ Wc,
                             const float* __restrict__ bfl, const float* __restrict__ bfr,
                             const float* __restrict__ bi,  const float* __restrict__ bo,
                             const float* __restrict__ bc) {
    int idx = blockIdx.x * blockDim.x + threadIdx.x;
    int stride = gridDim.x * blockDim.x;
    // gate weights: g_Wk[p][k], p = grp*160 + gate*32 + jj
    for (int i = idx; i < 1280 * 512; i += stride) {
        int p = i >> 9, k = i & 511;
        int grp = p / 160, rem = p - grp * 160;
        int g5 = rem >> 5, jj = rem & 31;
        const float* W = (g5 == 0) ? Wfl : (g5 == 1) ? Wfr : (g5 == 2) ? Wi : (g5 == 3) ? Wo : Wc;
        g_Wk[i] = rnd_tf32(W[k * 256 + grp * 32 + jj]);
    }
    // W_proj: g_WpK[n][k]
    for (int i = idx; i < 256 * 256; i += stride) {
        int n = i >> 8, k = i & 255;
        g_WpK[i] = rnd_tf32(Wp[k * 256 + n]);
    }
    for (size_t i = idx; i < (size_t)50000 * 256; i += stride) g_embR[i] = rnd_tf32(emb[i]);
    for (int i = idx; i < 1280; i += stride) {
        int grp = i / 160, rem = i - grp * 160;
        int g5 = rem >> 5, jj = rem & 31;
        const float* bb = (g5 == 0) ? bfl : (g5 == 1) ? bfr : (g5 == 2) ? bi : (g5 == 3) ? bo : bc;
        g_bt[i] = bb[grp * 32 + jj];
    }
}

// ================= LEVEL KERNEL (big levels) =================
// CTA 128 x 160 (32 ch x 5 gates), K=512, chunk=32, 2-stage, warps 4M x 2N (32x80).
#define ASTR 36
#define LV_AF (128 * ASTR)          // 4608 floats
#define LV_BF (160 * ASTR)          // 5760 floats (B n-major: 160 p-rows x 32k+pad)
#define LV_STGF (LV_AF + LV_BF)     // 10368
#define LV_SMEM (2 * LV_STGF * 4)   // 82944 bytes

__global__ __launch_bounds__(256, 2) void level_fused(const float* __restrict__ Hin,
                                                      const float* __restrict__ Cin,
                                                      float* __restrict__ Hout,
                                                      float* __restrict__ Cout, int Mout) {
    extern __shared__ float dsm[];
    __shared__ float s_bias[160];
    const int tid = threadIdx.x, wid = tid >> 5, lane = tid & 31;
    const int qr = lane >> 2, qc = lane & 3;
    const int wm = wid >> 1, wn = wid & 1;
    const int lrow = lane & 15;            // ldmatrix row within 16
    const int lk = (lane >> 4) << 2;       // ldmatrix k sub-offset (0 or 4)
    const int mBase = blockIdx.x * 128;
    const int grp = blockIdx.y;
    const int p0 = grp * 160, c0 = grp * 32;

    for (int i = tid; i < 160; i += 256) s_bias[i] = g_bt[p0 + i];

    float acc[2][10][4];
#pragma unroll
    for (int a = 0; a < 2; a++)
#pragma unroll
        for (int b = 0; b < 10; b++)
#pragma unroll
            for (int e = 0; e < 4; e++) acc[a][b][e] = 0.f;

    auto load_chunk = [&](int kc) {
        float* As = dsm + (kc & 1) * LV_STGF;
        float* Bs = As + LV_AF;
#pragma unroll
        for (int t = 0; t < 4; t++) {
            int v = tid + t * 256;
            int r = v >> 3, c = v & 7;
            int row = mBase + r; if (row >= Mout) row = Mout - 1;
            cp16(As + r * ASTR + c * 4, Hin + (size_t)row * 512 + kc * 32 + c * 4);
        }
#pragma unroll
        for (int t = 0; t < 5; t++) {
            int v = tid + t * 256;
            int r = v >> 3, c = v & 7;      // p-row 0..159, k 16B seg 0..7
            cp16(Bs + r * ASTR + c * 4, g_Wk + (size_t)(p0 + r) * 512 + kc * 32 + c * 4);
        }
        CP_COMMIT();
    };

    load_chunk(0);
    for (int i = 0; i < 16; i++) {
        if (i + 1 < 16) { load_chunk(i + 1); CP_WAIT1(); } else { CP_WAIT0(); }
        __syncthreads();
        const float* As = dsm + (i & 1) * LV_STGF;
        const float* Bs = As + LV_AF;
#pragma unroll
        for (int ks = 0; ks < 4; ks++) {
            uint32_t a0[4], a1[4];
            ldsm4(a0, As + (wm * 32 + lrow) * ASTR + ks * 8 + lk);
            ldsm4(a1, As + (wm * 32 + 16 + lrow) * ASTR + ks * 8 + lk);
            uint32_t bb[5][4];
#pragma unroll
            for (int j = 0; j < 5; j++)
                ldsm4(bb[j], Bs + (j * 32 + wn * 16 + lrow) * ASTR + ks * 8 + lk);
#pragma unroll
            for (int j = 0; j < 5; j++) {
                mma_tf32(acc[0][2 * j],     a0, bb[j][0], bb[j][2]);
                mma_tf32(acc[1][2 * j],     a1, bb[j][0], bb[j][2]);
                mma_tf32(acc[0][2 * j + 1], a0, bb[j][1], bb[j][3]);
                mma_tf32(acc[1][2 * j + 1], a1, bb[j][1], bb[j][3]);
            }
        }
        __syncthreads();
    }

    // fused gate epilogue (identical acc semantics to R7)
#pragma unroll
    for (int ma = 0; ma < 2; ma++) {
#pragma unroll
        for (int eh = 0; eh < 2; eh++) {
            int row = mBase + wm * 32 + ma * 16 + qr + eh * 8;
            if (row < Mout) {
#pragma unroll
                for (int na = 0; na < 2; na++) {
                    int jj = wn * 16 + na * 8 + qc * 2;
                    float2 cl = *(const float2*)(Cin + (size_t)row * 512 + c0 + jj);
                    float2 cr = *(const float2*)(Cin + (size_t)row * 512 + 256 + c0 + jj);
                    float hv[2], cv[2];
#pragma unroll
                    for (int e = 0; e < 2; e++) {
                        int bi_ = jj + e;
                        float fl = sigm(acc[ma][0 * 2 + na][eh * 2 + e] + s_bias[0 * 32 + bi_]);
                        float fr = sigm(acc[ma][1 * 2 + na][eh * 2 + e] + s_bias[1 * 32 + bi_]);
                        float ig = sigm(acc[ma][2 * 2 + na][eh * 2 + e] + s_bias[2 * 32 + bi_]);
                        float og = sigm(acc[ma][3 * 2 + na][eh * 2 + e] + s_bias[3 * 32 + bi_]);
                        float cc = tanhf(acc[ma][4 * 2 + na][eh * 2 + e] + s_bias[4 * 32 + bi_]);
                        float clv = (e == 0) ? cl.x : cl.y;
                        float crv = (e == 0) ? cr.x : cr.y;
                        float cn = fl * clv + fr * crv + ig * cc;
                        cv[e] = cn;
                        hv[e] = rnd_tf32(og * tanhf(cn));
                    }
                    *(float2*)(Hout + (size_t)row * 256 + c0 + jj) = make_float2(hv[0], hv[1]);
                    *(float2*)(Cout + (size_t)row * 256 + c0 + jj) = make_float2(cv[0], cv[1]);
                }
            }
        }
    }
}

// ================= LEAF KERNEL =================
#define LF_AF (128 * ASTR)          // 4608
#define LF_BF (128 * ASTR)          // 4608 (128 n-rows)
#define LF_STGF (LF_AF + LF_BF)     // 9216
#define LF_SMEM (2 * LF_STGF * 4)   // 73728

__global__ __launch_bounds__(256, 2) void leaf_fused(const int* __restrict__ ids,
                                                     const float* __restrict__ bp,
                                                     float* __restrict__ Hout,
                                                     float* __restrict__ Cout) {
    extern __shared__ float dsm[];
    __shared__ int s_ids[128];
    __shared__ float s_bp[128];
    const int tid = threadIdx.x, wid = tid >> 5, lane = tid & 31;
    const int qr = lane >> 2, qc = lane & 3;
    const int wm = wid >> 1, wn = wid & 1;
    const int lrow = lane & 15;
    const int lk = (lane >> 4) << 2;
    const int mBase = blockIdx.x * 128;
    const int nBase = blockIdx.y * 128;

    if (tid < 128) {
        s_ids[tid] = ids[mBase + tid];
        s_bp[tid] = bp[nBase + tid];
    }
    __syncthreads();

    float acc[2][8][4];
#pragma unroll
    for (int a = 0; a < 2; a++)
#pragma unroll
        for (int b = 0; b < 8; b++)
#pragma unroll
            for (int e = 0; e < 4; e++) acc[a][b][e] = 0.f;

    auto load_chunk = [&](int kc) {
        float* As = dsm + (kc & 1) * LF_STGF;
        float* Bs = As + LF_AF;
#pragma unroll
        for (int t = 0; t < 4; t++) {
            int v = tid + t * 256;
            int r = v >> 3, c = v & 7;
            cp16(As + r * ASTR + c * 4, g_embR + (size_t)s_ids[r] * 256 + kc * 32 + c * 4);
        }
#pragma unroll
        for (int t = 0; t < 4; t++) {
            int v = tid + t * 256;
            int r = v >> 3, c = v & 7;
            cp16(Bs + r * ASTR + c * 4, g_WpK + (size_t)(nBase + r) * 256 + kc * 32 + c * 4);
        }
        CP_COMMIT();
    };

    load_chunk(0);
    for (int i = 0; i < 8; i++) {
        if (i + 1 < 8) { load_chunk(i + 1); CP_WAIT1(); } else { CP_WAIT0(); }
        __syncthreads();
        const float* As = dsm + (i & 1) * LF_STGF;
        const float* Bs = As + LF_AF;
#pragma unroll
        for (int ks = 0; ks < 4; ks++) {
            uint32_t a0[4], a1[4];
            ldsm4(a0, As + (wm * 32 + lrow) * ASTR + ks * 8 + lk);
            ldsm4(a1, As + (wm * 32 + 16 + lrow) * ASTR + ks * 8 + lk);
            uint32_t bb[4][4];
#pragma unroll
            for (int j = 0; j < 4; j++)
                ldsm4(bb[j], Bs + (wn * 64 + j * 16 + lrow) * ASTR + ks * 8 + lk);
#pragma unroll
            for (int j = 0; j < 4; j++) {
                mma_tf32(acc[0][2 * j],     a0, bb[j][0], bb[j][2]);
                mma_tf32(acc[1][2 * j],     a1, bb[j][0], bb[j][2]);
                mma_tf32(acc[0][2 * j + 1], a0, bb[j][1], bb[j][3]);
                mma_tf32(acc[1][2 * j + 1], a1, bb[j][1], bb[j][3]);
            }
        }
        __syncthreads();
    }

#pragma unroll
    for (int ma = 0; ma < 2; ma++) {
#pragma unroll
        for (int eh = 0; eh < 2; eh++) {
            int row = mBase + wm * 32 + ma * 16 + qr + eh * 8;
#pragma unroll
            for (int na = 0; na < 8; na++) {
                int cl = wn * 64 + na * 8 + qc * 2;
                float h0 = acc[ma][na][eh * 2 + 0] + s_bp[cl + 0];
                float h1 = acc[ma][na][eh * 2 + 1] + s_bp[cl + 1];
                *(float2*)(Hout + (size_t)row * 256 + nBase + cl) =
                    make_float2(rnd_tf32(h0), rnd_tf32(h1));
                *(float2*)(Cout + (size_t)row * 256 + nBase + cl) =
                    make_float2(tanhf(h0), tanhf(h1));
            }
        }
    }
}

// ================= PERSISTENT SMALL-LEVELS KERNEL =================
// Tile 64 x 160, warps 4M(16) x 2N(80). 2-stage.
#define SL_GRID 128
#define SL_AF (64 * ASTR)           // 2304
#define SL_BF (160 * ASTR)          // 5760
#define SL_STGF (SL_AF + SL_BF)     // 8064
#define SL_SMEM (2 * SL_STGF * 4)   // 64512

__global__ __launch_bounds__(256, 1) void small_levels(float* __restrict__ inH0,
                                                       float* __restrict__ inC0,
                                                       float* __restrict__ outH0,
                                                       float* __restrict__ outC0,
                                                       const float* __restrict__ Wcls,
                                                       const float* __restrict__ bcls,
                                                       float* __restrict__ out) {
    extern __shared__ float dsm[];
    __shared__ float s_bias[160];
    const int tid = threadIdx.x, wid = tid >> 5, lane = tid & 31;
    const int qr = lane >> 2, qc = lane & 3;
    const int wm = wid >> 1, wn = wid & 1;
    const int lrow = lane & 15;
    const int lk = (lane >> 4) << 2;

    unsigned gen = 0;
    if (tid == 0) gen = *(volatile unsigned*)&g_bar_gen;

    float* inH = inH0;  float* inC = inC0;
    float* outH = outH0; float* outC = outC0;

    int cur = 4096;
    while (cur > 16) {
        const int Mout = cur >> 1;
        const int mtiles = (Mout + 63) >> 6;
        const int nt = mtiles * 8;
        for (int t = blockIdx.x; t < nt; t += SL_GRID) {
            const int grp = t / mtiles;
            const int mtile = t - grp * mtiles;
            const int p0 = grp * 160, c0 = grp * 32;
            const int mBase = mtile * 64;

            for (int i = tid; i < 160; i += 256) s_bias[i] = g_bt[p0 + i];

            float acc[10][4];
#pragma unroll
            for (int b = 0; b < 10; b++)
#pragma unroll
                for (int e = 0; e < 4; e++) acc[b][e] = 0.f;

            auto load_chunk = [&](int kc) {
                float* As = dsm + (kc & 1) * SL_STGF;
                float* Bs = As + SL_AF;
#pragma unroll
                for (int tt = 0; tt < 2; tt++) {
                    int v = tid + tt * 256;
                    int r = v >> 3, c = v & 7;
                    int row = mBase + r; if (row >= Mout) row = Mout - 1;
                    cp16(As + r * ASTR + c * 4, inH + (size_t)row * 512 + kc * 32 + c * 4);
                }
#pragma unroll
                for (int tt = 0; tt < 5; tt++) {
                    int v = tid + tt * 256;
                    int r = v >> 3, c = v & 7;
                    cp16(Bs + r * ASTR + c * 4, g_Wk + (size_t)(p0 + r) * 512 + kc * 32 + c * 4);
                }
                CP_COMMIT();
            };

            load_chunk(0);
            for (int i = 0; i < 16; i++) {
                if (i + 1 < 16) { load_chunk(i + 1); CP_WAIT1(); } else { CP_WAIT0(); }
                __syncthreads();
                const float* As = dsm + (i & 1) * SL_STGF;
                const float* Bs = As + SL_AF;
#pragma unroll
                for (int ks = 0; ks < 4; ks++) {
                    uint32_t a0[4];
                    ldsm4(a0, As + (wm * 16 + lrow) * ASTR + ks * 8 + lk);
                    uint32_t bb[5][4];
#pragma unroll
                    for (int j = 0; j < 5; j++)
                        ldsm4(bb[j], Bs + (j * 32 + wn * 16 + lrow) * ASTR + ks * 8 + lk);
#pragma unroll
                    for (int j = 0; j < 5; j++) {
                        mma_tf32(acc[2 * j],     a0, bb[j][0], bb[j][2]);
                        mma_tf32(acc[2 * j + 1], a0, bb[j][1], bb[j][3]);
                    }
                }
                __syncthreads();
            }

#pragma unroll
            for (int eh = 0; eh < 2; eh++) {
                int row = mBase + wm * 16 + qr + eh * 8;
                if (row < Mout) {
#pragma unroll
                    for (int na = 0; na < 2; na++) {
                        int jj = wn * 16 + na * 8 + qc * 2;
                        float2 cl = *(const float2*)(inC + (size_t)row * 512 + c0 + jj);
                        float2 cr = *(const float2*)(inC + (size_t)row * 512 + 256 + c0 + jj);
                        float hv[2], cv[2];
#pragma unroll
                        for (int e = 0; e < 2; e++) {
                            int bi_ = jj + e;
                            float fl = sigm(acc[0 * 2 + na][eh * 2 + e] + s_bias[0 * 32 + bi_]);
                            float fr = sigm(acc[1 * 2 + na][eh * 2 + e] + s_bias[1 * 32 + bi_]);
                            float ig = sigm(acc[2 * 2 + na][eh * 2 + e] + s_bias[2 * 32 + bi_]);
                            float og = sigm(acc[3 * 2 + na][eh * 2 + e] + s_bias[3 * 32 + bi_]);
                            float cc = tanhf(acc[4 * 2 + na][eh * 2 + e] + s_bias[4 * 32 + bi_]);
                            float clv = (e == 0) ? cl.x : cl.y;
                            float crv = (e == 0) ? cr.x : cr.y;
                            float cn = fl * clv + fr * crv + ig * cc;
                            cv[e] = cn;
                            hv[e] = rnd_tf32(og * tanhf(cn));
                        }
                        *(float2*)(outH + (size_t)row * 256 + c0 + jj) = make_float2(hv[0], hv[1]);
                        *(float2*)(outC + (size_t)row * 256 + c0 + jj) = make_float2(cv[0], cv[1]);
                    }
                }
            }
            __syncthreads();
        }

        // -------- grid-wide barrier --------
        __threadfence();
        __syncthreads();
        if (tid == 0) {
            unsigned arrived = atomicAdd(&g_bar_cnt, 1u);
            if (arrived == SL_GRID - 1) {
                g_bar_cnt = 0;
                __threadfence();
                atomicAdd(&g_bar_gen, 1u);
                gen++;
            } else {
                unsigned cg;
                do {
                    __nanosleep(64);
                    asm volatile("ld.acquire.gpu.u32 %0, [%1];" : "=r"(cg) : "l"(&g_bar_gen) : "memory");
                } while (cg == gen);
                gen = cg;
                __threadfence();
            }
        }
        __syncthreads();

        float* th = inH; inH = outH; outH = th;
        float* tc = inC; inC = outC; outC = tc;
        cur = Mout;
    }

    // classifier on root H — CTA 0
    if (blockIdx.x == 0 && tid < BVAL * 2) {
        int b = tid >> 1, cx = tid & 1;
        float sum = bcls[cx];
        const float* h = inH + (size_t)b * HVAL;
        for (int k = 0; k < HVAL; k++) sum += h[k] * Wcls[k * 2 + cx];
        out[b * 2 + cx] = sum;
    }
}

// ---------------- launch ----------------
extern "C" void kernel_launch(void* const* d_in, const int* in_sizes, int n_in,
                              void* d_out, int out_size) {
    const int*   leaf_ids = (const int*)d_in[0];
    const float* emb  = (const float*)d_in[1];
    const float* Wp   = (const float*)d_in[2];
    const float* bp   = (const float*)d_in[3];
    const float* Wfl  = (const float*)d_in[4];
    const float* bfl  = (const float*)d_in[5];
    const float* Wfr  = (const float*)d_in[6];
    const float* bfr  = (const float*)d_in[7];
    const float* Wi   = (const float*)d_in[8];
    const float* bi   = (const float*)d_in[9];
    const float* Wo   = (const float*)d_in[10];
    const float* bo   = (const float*)d_in[11];
    const float* Wc   = (const float*)d_in[12];
    const float* bc   = (const float*)d_in[13];
    const float* Wcls = (const float*)d_in[14];
    const float* bcls = (const float*)d_in[15];
    float* out = (float*)d_out;

    float *Ah, *Ac, *Bh, *Bc;
    cudaGetSymbolAddress((void**)&Ah, g_bufA_h);
    cudaGetSymbolAddress((void**)&Ac, g_bufA_c);
    cudaGetSymbolAddress((void**)&Bh, g_bufB_h);
    cudaGetSymbolAddress((void**)&Bc, g_bufB_c);

    cudaFuncSetAttribute(level_fused,  cudaFuncAttributeMaxDynamicSharedMemorySize, LV_SMEM);
    cudaFuncSetAttribute(leaf_fused,   cudaFuncAttributeMaxDynamicSharedMemorySize, LF_SMEM);
    cudaFuncSetAttribute(small_levels, cudaFuncAttributeMaxDynamicSharedMemorySize, SL_SMEM);

    pack_weights<<<1024, 256>>>(emb, Wp, Wfl, Wfr, Wi, Wo, Wc, bfl, bfr, bi, bo, bc);

    leaf_fused<<<dim3(NODES0 / 128, 2), 256, LF_SMEM>>>(leaf_ids, bp, Ah, Ac);

    float *inH = Ah, *inC = Ac, *outH = Bh, *outC = Bc;
    int cur = NODES0;
    while (cur > 4096) {
        int Mout = cur >> 1;
        dim3 grid(Mout / 128, 8);
        level_fused<<<grid, 256, LV_SMEM>>>(inH, inC, outH, outC, Mout);
        float* t;
        t = inH; inH = outH; outH = t;
        t = inC; inC = outC; outC = t;
        cur = Mout;
    }

    small_levels<<<SL_GRID, 256, SL_SMEM>>>(inH, inC, outH, outC, Wcls, bcls, out);
}

// round 11
// speedup vs baseline: 1.2688x; 1.0987x over previous
#include <cuda_runtime.h>
#include <cstdint>
#include <math.h>

#define BVAL 16
#define HVAL 256
#define NODES0 65536

// ---------------- device scratch ----------------
__device__ __align__(16) float g_bufA_h[(size_t)NODES0 * HVAL];
__device__ __align__(16) float g_bufA_c[(size_t)NODES0 * HVAL];
__device__ __align__(16) float g_bufB_h[(size_t)(NODES0 / 2) * HVAL];
__device__ __align__(16) float g_bufB_c[(size_t)(NODES0 / 2) * HVAL];
// g_Wk chunk images: [kc(16)][r(16)=ks*4+qc][p(1280)][pair(2)]; pair=(k, k+4), k=kc*32+ks*8+qc
__device__ __align__(16) float g_Wk[(size_t)16 * 16 * 1280 * 2];
// g_WpK flat [k(256)][n(256)], tf32-RN
__device__ __align__(16) float g_WpK[(size_t)256 * 256];
__device__ __align__(16) float g_bt[1280];                  // packed gate biases

__device__ unsigned g_bar_cnt = 0;
__device__ unsigned g_bar_gen = 0;

// ---------------- helpers ----------------
__device__ __forceinline__ float rnd_tf32(float x) {
    uint32_t r;
    asm("cvt.rna.tf32.f32 %0, %1;" : "=r"(r) : "f"(x));
    return __uint_as_float(r);
}
__device__ __forceinline__ float sigm(float x) { return 1.0f / (1.0f + __expf(-x)); }

__device__ __forceinline__ void cp16(void* dst, const float* src) {
    uint32_t d = (uint32_t)__cvta_generic_to_shared(dst);
    asm volatile("cp.async.cg.shared.global [%0], [%1], 16;"
                 :: "r"(d), "l"(__cvta_generic_to_global(src)));
}
#define CP_COMMIT() asm volatile("cp.async.commit_group;" ::: "memory")
#define CP_WAIT1()  asm volatile("cp.async.wait_group 1;" ::: "memory")
#define CP_WAIT0()  asm volatile("cp.async.wait_group 0;" ::: "memory")

__device__ __forceinline__ void mma_tf32(float* c, const uint32_t* a, uint32_t b0, uint32_t b1) {
    asm volatile("mma.sync.aligned.m16n8k8.row.col.f32.tf32.tf32.f32 "
                 "{%0,%1,%2,%3}, {%4,%5,%6,%7}, {%8,%9}, {%0,%1,%2,%3};"
                 : "+f"(c[0]), "+f"(c[1]), "+f"(c[2]), "+f"(c[3])
                 : "r"(a[0]), "r"(a[1]), "r"(a[2]), "r"(a[3]), "r"(b0), "r"(b1));
}

// ---------------- pack kernel (weights only) ----------------
__global__ void pack_weights(const float* __restrict__ Wp,
                             const float* __restrict__ Wfl, const float* __restrict__ Wfr,
                             const float* __restrict__ Wi,  const float* __restrict__ Wo,
                             const float* __restrict__ Wc,
                             const float* __restrict__ bfl, const float* __restrict__ bfr,
                             const float* __restrict__ bi,  const float* __restrict__ bo,
                             const float* __restrict__ bc) {
    int idx = blockIdx.x * blockDim.x + threadIdx.x;
    int stride = gridDim.x * blockDim.x;
    // gate weights pair-chunk images
    for (int i = idx; i < 16 * 16 * 1280 * 2; i += stride) {
        int e = i & 1;
        int t = i >> 1;
        int p = t % 1280;
        int rr = t / 1280;
        int r = rr & 15, kc = rr >> 4;
        int k = kc * 32 + (r >> 2) * 8 + (r & 3) + e * 4;
        int grp = p / 160, rem = p - grp * 160;
        int g5 = rem >> 5, jj = rem & 31;
        const float* W = (g5 == 0) ? Wfl : (g5 == 1) ? Wfr : (g5 == 2) ? Wi : (g5 == 3) ? Wo : Wc;
        g_Wk[i] = rnd_tf32(W[k * 256 + grp * 32 + jj]);
    }
    // W_proj flat [k][n]
    for (int i = idx; i < 256 * 256; i += stride) g_WpK[i] = rnd_tf32(Wp[i]);
    for (int i = idx; i < 1280; i += stride) {
        int grp = i / 160, rem = i - grp * 160;
        int g5 = rem >> 5, jj = rem & 31;
        const float* bb = (g5 == 0) ? bfl : (g5 == 1) ? bfr : (g5 == 2) ? bi : (g5 == 3) ? bo : bc;
        g_bt[i] = bb[grp * 32 + jj];
    }
}

// ================= LEVEL KERNEL (big levels) — R7 verbatim =================
#define ASTR 36
#define BSTR2 328
#define LV_AF (128 * ASTR)          // 4608
#define LV_BF (16 * BSTR2)          // 5248
#define LV_STGF (LV_AF + LV_BF)     // 9856
#define LV_SMEM (2 * LV_STGF * 4)   // 78848

__global__ __launch_bounds__(256, 2) void level_fused(const float* __restrict__ Hin,
                                                      const float* __restrict__ Cin,
                                                      float* __restrict__ Hout,
                                                      float* __restrict__ Cout, int Mout) {
    extern __shared__ float dsm[];
    __shared__ float s_bias[160];
    const int tid = threadIdx.x, wid = tid >> 5, lane = tid & 31;
    const int qr = lane >> 2, qc = lane & 3;
    const int wm = wid >> 1, wn = wid & 1;
    const int mBase = blockIdx.x * 128;
    const int grp = blockIdx.y;
    const int p0 = grp * 160, c0 = grp * 32;

    for (int i = tid; i < 160; i += 256) s_bias[i] = g_bt[p0 + i];

    float acc[2][10][4];
#pragma unroll
    for (int a = 0; a < 2; a++)
#pragma unroll
        for (int b = 0; b < 10; b++)
#pragma unroll
            for (int e = 0; e < 4; e++) acc[a][b][e] = 0.f;

    auto load_chunk = [&](int kc) {
        float* As = dsm + (kc & 1) * LV_STGF;
        float* Bs = As + LV_AF;
#pragma unroll
        for (int t = 0; t < 4; t++) {
            int v = tid + t * 256;
            int r = v >> 3, c = v & 7;
            int row = mBase + r; if (row >= Mout) row = Mout - 1;
            cp16(As + r * ASTR + c * 4, Hin + (size_t)row * 512 + kc * 32 + c * 4);
        }
#pragma unroll
        for (int t = 0; t < 5; t++) {
            int v = tid + t * 256;
            int kr = v / 80, c4 = v - kr * 80;
            cp16(Bs + kr * BSTR2 + c4 * 4,
                 g_Wk + (size_t)(kc * 16 + kr) * 2560 + p0 * 2 + c4 * 4);
        }
        CP_COMMIT();
    };

    load_chunk(0);
    for (int i = 0; i < 16; i++) {
        if (i + 1 < 16) { load_chunk(i + 1); CP_WAIT1(); } else { CP_WAIT0(); }
        __syncthreads();
        const float* As = dsm + (i & 1) * LV_STGF;
        const float* Bs = As + LV_AF;
#pragma unroll
        for (int ks = 0; ks < 4; ks++) {
            uint32_t a[2][4];
#pragma unroll
            for (int ma = 0; ma < 2; ma++) {
                const float* ap = As + (wm * 32 + ma * 16 + qr) * ASTR + ks * 8 + qc;
                a[ma][0] = __float_as_uint(ap[0]);
                a[ma][1] = __float_as_uint(ap[8 * ASTR]);
                a[ma][2] = __float_as_uint(ap[4]);
                a[ma][3] = __float_as_uint(ap[8 * ASTR + 4]);
            }
            const float* brow = Bs + (ks * 4 + qc) * BSTR2;
#pragma unroll
            for (int na = 0; na < 10; na++) {
                int col = (na >> 1) * 32 + wn * 16 + (na & 1) * 8 + qr;
                float2 bf = *(const float2*)(brow + col * 2);
                uint32_t b0 = __float_as_uint(bf.x);
                uint32_t b1 = __float_as_uint(bf.y);
                mma_tf32(acc[0][na], a[0], b0, b1);
                mma_tf32(acc[1][na], a[1], b0, b1);
            }
        }
        __syncthreads();
    }

#pragma unroll
    for (int ma = 0; ma < 2; ma++) {
#pragma unroll
        for (int eh = 0; eh < 2; eh++) {
            int row = mBase + wm * 32 + ma * 16 + qr + eh * 8;
            if (row < Mout) {
#pragma unroll
                for (int na = 0; na < 2; na++) {
                    int jj = wn * 16 + na * 8 + qc * 2;
                    float2 cl = *(const float2*)(Cin + (size_t)row * 512 + c0 + jj);
                    float2 cr = *(const float2*)(Cin + (size_t)row * 512 + 256 + c0 + jj);
                    float hv[2], cv[2];
#pragma unroll
                    for (int e = 0; e < 2; e++) {
                        int bi_ = jj + e;
                        float fl = sigm(acc[ma][0 * 2 + na][eh * 2 + e] + s_bias[0 * 32 + bi_]);
                        float fr = sigm(acc[ma][1 * 2 + na][eh * 2 + e] + s_bias[1 * 32 + bi_]);
                        float ig = sigm(acc[ma][2 * 2 + na][eh * 2 + e] + s_bias[2 * 32 + bi_]);
                        float og = sigm(acc[ma][3 * 2 + na][eh * 2 + e] + s_bias[3 * 32 + bi_]);
                        float cc = tanhf(acc[ma][4 * 2 + na][eh * 2 + e] + s_bias[4 * 32 + bi_]);
                        float clv = (e == 0) ? cl.x : cl.y;
                        float crv = (e == 0) ? cr.x : cr.y;
                        float cn = fl * clv + fr * crv + ig * cc;
                        cv[e] = cn;
                        hv[e] = rnd_tf32(og * tanhf(cn));
                    }
                    *(float2*)(Hout + (size_t)row * 256 + c0 + jj) = make_float2(hv[0], hv[1]);
                    *(float2*)(Cout + (size_t)row * 256 + c0 + jj) = make_float2(cv[0], cv[1]);
                }
            }
        }
    }
}

// ================= LEAF KERNEL — R8 verbatim (direct emb + in-reg tf32) =================
#define BSTRL 136
#define LF_AF (128 * ASTR)          // 4608
#define LF_BF (32 * BSTRL)          // 4352
#define LF_STGF (LF_AF + LF_BF)     // 8960
#define LF_SMEM (2 * LF_STGF * 4)   // 71680

__global__ __launch_bounds__(256, 2) void leaf_fused(const int* __restrict__ ids,
                                                     const float* __restrict__ emb,
                                                     const float* __restrict__ bp,
                                                     float* __restrict__ Hout,
                                                     float* __restrict__ Cout) {
    extern __shared__ float dsm[];
    __shared__ int s_ids[128];
    __shared__ float s_bp[128];
    const int tid = threadIdx.x, wid = tid >> 5, lane = tid & 31;
    const int qr = lane >> 2, qc = lane & 3;
    const int wm = wid >> 1, wn = wid & 1;
    const int mBase = blockIdx.x * 128;
    const int nBase = blockIdx.y * 128;

    if (tid < 128) {
        s_ids[tid] = ids[mBase + tid];
        s_bp[tid] = bp[nBase + tid];
    }
    __syncthreads();

    float acc[2][8][4];
#pragma unroll
    for (int a = 0; a < 2; a++)
#pragma unroll
        for (int b = 0; b < 8; b++)
#pragma unroll
            for (int e = 0; e < 4; e++) acc[a][b][e] = 0.f;

    auto load_chunk = [&](int kc) {
        float* As = dsm + (kc & 1) * LF_STGF;
        float* Bs = As + LF_AF;
#pragma unroll
        for (int t = 0; t < 4; t++) {
            int v = tid + t * 256;
            int r = v >> 3, c = v & 7;
            cp16(As + r * ASTR + c * 4, emb + (size_t)s_ids[r] * 256 + kc * 32 + c * 4);
        }
#pragma unroll
        for (int t = 0; t < 4; t++) {
            int v = tid + t * 256;
            int kr = v >> 5, c4 = v & 31;
            cp16(Bs + kr * BSTRL + c4 * 4, g_WpK + (size_t)(kc * 32 + kr) * 256 + nBase + c4 * 4);
        }
        CP_COMMIT();
    };

    load_chunk(0);
    for (int i = 0; i < 8; i++) {
        if (i + 1 < 8) { load_chunk(i + 1); CP_WAIT1(); } else { CP_WAIT0(); }
        __syncthreads();
        const float* As = dsm + (i & 1) * LF_STGF;
        const float* Bs = As + LF_AF;
#pragma unroll
        for (int ks = 0; ks < 4; ks++) {
            uint32_t a[2][4];
#pragma unroll
            for (int ma = 0; ma < 2; ma++) {
                const float* ap = As + (wm * 32 + ma * 16 + qr) * ASTR + ks * 8 + qc;
                a[ma][0] = __float_as_uint(rnd_tf32(ap[0]));
                a[ma][1] = __float_as_uint(rnd_tf32(ap[8 * ASTR]));
                a[ma][2] = __float_as_uint(rnd_tf32(ap[4]));
                a[ma][3] = __float_as_uint(rnd_tf32(ap[8 * ASTR + 4]));
            }
            const float* brow = Bs + (ks * 8 + qc) * BSTRL;
#pragma unroll
            for (int na = 0; na < 8; na++) {
                int col = wn * 64 + na * 8 + qr;
                uint32_t b0 = __float_as_uint(brow[col]);
                uint32_t b1 = __float_as_uint(brow[4 * BSTRL + col]);
                mma_tf32(acc[0][na], a[0], b0, b1);
                mma_tf32(acc[1][na], a[1], b0, b1);
            }
        }
        __syncthreads();
    }

#pragma unroll
    for (int ma = 0; ma < 2; ma++) {
#pragma unroll
        for (int eh = 0; eh < 2; eh++) {
            int row = mBase + wm * 32 + ma * 16 + qr + eh * 8;
#pragma unroll
            for (int na = 0; na < 8; na++) {
                int cl = wn * 64 + na * 8 + qc * 2;
                float h0 = acc[ma][na][eh * 2 + 0] + s_bp[cl + 0];
                float h1 = acc[ma][na][eh * 2 + 1] + s_bp[cl + 1];
                *(float2*)(Hout + (size_t)row * 256 + nBase + cl) =
                    make_float2(rnd_tf32(h0), rnd_tf32(h1));
                *(float2*)(Cout + (size_t)row * 256 + nBase + cl) =
                    make_float2(tanhf(h0), tanhf(h1));
            }
        }
    }
}

// ================= PERSISTENT SMALL-LEVELS KERNEL — R7 verbatim =================
#define SL_GRID 128
#define SL_AF (64 * ASTR)           // 2304
#define SL_BF (16 * BSTR2)          // 5248
#define SL_STGF (SL_AF + SL_BF)     // 7552
#define SL_SMEM (2 * SL_STGF * 4)   // 60416

__global__ __launch_bounds__(256, 1) void small_levels(float* __restrict__ inH0,
                                                       float* __restrict__ inC0,
                                                       float* __restrict__ outH0,
                                                       float* __restrict__ outC0,
                                                       const float* __restrict__ Wcls,
                                                       const float* __restrict__ bcls,
                                                       float* __restrict__ out) {
    extern __shared__ float dsm[];
    __shared__ float s_bias[160];
    const int tid = threadIdx.x, wid = tid >> 5, lane = tid & 31;
    const int qr = lane >> 2, qc = lane & 3;
    const int wm = wid >> 1, wn = wid & 1;

    unsigned gen = 0;
    if (tid == 0) gen = *(volatile unsigned*)&g_bar_gen;

    float* inH = inH0;  float* inC = inC0;
    float* outH = outH0; float* outC = outC0;

    int cur = 4096;
    while (cur > 16) {
        const int Mout = cur >> 1;
        const int mtiles = (Mout + 63) >> 6;
        const int nt = mtiles * 8;
        for (int t = blockIdx.x; t < nt; t += SL_GRID) {
            const int grp = t / mtiles;
            const int mtile = t - grp * mtiles;
            const int p0 = grp * 160, c0 = grp * 32;
            const int mBase = mtile * 64;

            for (int i = tid; i < 160; i += 256) s_bias[i] = g_bt[p0 + i];

            float acc[10][4];
#pragma unroll
            for (int b = 0; b < 10; b++)
#pragma unroll
                for (int e = 0; e < 4; e++) acc[b][e] = 0.f;

            auto load_chunk = [&](int kc) {
                float* As = dsm + (kc & 1) * SL_STGF;
                float* Bs = As + SL_AF;
#pragma unroll
                for (int tt = 0; tt < 2; tt++) {
                    int v = tid + tt * 256;
                    int r = v >> 3, c = v & 7;
                    int row = mBase + r; if (row >= Mout) row = Mout - 1;
                    cp16(As + r * ASTR + c * 4, inH + (size_t)row * 512 + kc * 32 + c * 4);
                }
#pragma unroll
                for (int tt = 0; tt < 5; tt++) {
                    int v = tid + tt * 256;
                    int kr = v / 80, c4 = v - kr * 80;
                    cp16(Bs + kr * BSTR2 + c4 * 4,
                         g_Wk + (size_t)(kc * 16 + kr) * 2560 + p0 * 2 + c4 * 4);
                }
                CP_COMMIT();
            };

            load_chunk(0);
            for (int i = 0; i < 16; i++) {
                if (i + 1 < 16) { load_chunk(i + 1); CP_WAIT1(); } else { CP_WAIT0(); }
                __syncthreads();
                const float* As = dsm + (i & 1) * SL_STGF;
                const float* Bs = As + SL_AF;
#pragma unroll
                for (int ks = 0; ks < 4; ks++) {
                    uint32_t a[4];
                    const float* ap = As + (wm * 16 + qr) * ASTR + ks * 8 + qc;
                    a[0] = __float_as_uint(ap[0]);
                    a[1] = __float_as_uint(ap[8 * ASTR]);
                    a[2] = __float_as_uint(ap[4]);
                    a[3] = __float_as_uint(ap[8 * ASTR + 4]);
                    const float* brow = Bs + (ks * 4 + qc) * BSTR2;
#pragma unroll
                    for (int na = 0; na < 10; na++) {
                        int col = (na >> 1) * 32 + wn * 16 + (na & 1) * 8 + qr;
                        float2 bf = *(const float2*)(brow + col * 2);
                        mma_tf32(acc[na], a, __float_as_uint(bf.x), __float_as_uint(bf.y));
                    }
                }
                __syncthreads();
            }

#pragma unroll
            for (int eh = 0; eh < 2; eh++) {
                int row = mBase + wm * 16 + qr + eh * 8;
                if (row < Mout) {
#pragma unroll
                    for (int na = 0; na < 2; na++) {
                        int jj = wn * 16 + na * 8 + qc * 2;
                        float2 cl = *(const float2*)(inC + (size_t)row * 512 + c0 + jj);
                        float2 cr = *(const float2*)(inC + (size_t)row * 512 + 256 + c0 + jj);
                        float hv[2], cv[2];
#pragma unroll
                        for (int e = 0; e < 2; e++) {
                            int bi_ = jj + e;
                            float fl = sigm(acc[0 * 2 + na][eh * 2 + e] + s_bias[0 * 32 + bi_]);
                            float fr = sigm(acc[1 * 2 + na][eh * 2 + e] + s_bias[1 * 32 + bi_]);
                            float ig = sigm(acc[2 * 2 + na][eh * 2 + e] + s_bias[2 * 32 + bi_]);
                            float og = sigm(acc[3 * 2 + na][eh * 2 + e] + s_bias[3 * 32 + bi_]);
                            float cc = tanhf(acc[4 * 2 + na][eh * 2 + e] + s_bias[4 * 32 + bi_]);
                            float clv = (e == 0) ? cl.x : cl.y;
                            float crv = (e == 0) ? cr.x : cr.y;
                            float cn = fl * clv + fr * crv + ig * cc;
                            cv[e] = cn;
                            hv[e] = rnd_tf32(og * tanhf(cn));
                        }
                        *(float2*)(outH + (size_t)row * 256 + c0 + jj) = make_float2(hv[0], hv[1]);
                        *(float2*)(outC + (size_t)row * 256 + c0 + jj) = make_float2(cv[0], cv[1]);
                    }
                }
            }
            __syncthreads();
        }

        // -------- grid-wide barrier --------
        __threadfence();
        __syncthreads();
        if (tid == 0) {
            unsigned arrived = atomicAdd(&g_bar_cnt, 1u);
            if (arrived == SL_GRID - 1) {
                g_bar_cnt = 0;
                __threadfence();
                atomicAdd(&g_bar_gen, 1u);
                gen++;
            } else {
                unsigned cg;
                do {
                    __nanosleep(64);
                    asm volatile("ld.acquire.gpu.u32 %0, [%1];" : "=r"(cg) : "l"(&g_bar_gen) : "memory");
                } while (cg == gen);
                gen = cg;
                __threadfence();
            }
        }
        __syncthreads();

        float* th = inH; inH = outH; outH = th;
        float* tc = inC; inC = outC; outC = tc;
        cur = Mout;
    }

    // classifier on root H — CTA 0
    if (blockIdx.x == 0 && tid < BVAL * 2) {
        int b = tid >> 1, cx = tid & 1;
        float sum = bcls[cx];
        const float* h = inH + (size_t)b * HVAL;
        for (int k = 0; k < HVAL; k++) sum += h[k] * Wcls[k * 2 + cx];
        out[b * 2 + cx] = sum;
    }
}

// ---------------- launch ----------------
extern "C" void kernel_launch(void* const* d_in, const int* in_sizes, int n_in,
                              void* d_out, int out_size) {
    const int*   leaf_ids = (const int*)d_in[0];
    const float* emb  = (const float*)d_in[1];
    const float* Wp   = (const float*)d_in[2];
    const float* bp   = (const float*)d_in[3];
    const float* Wfl  = (const float*)d_in[4];
    const float* bfl  = (const float*)d_in[5];
    const float* Wfr  = (const float*)d_in[6];
    const float* bfr  = (const float*)d_in[7];
    const float* Wi   = (const float*)d_in[8];
    const float* bi   = (const float*)d_in[9];
    const float* Wo   = (const float*)d_in[10];
    const float* bo   = (const float*)d_in[11];
    const float* Wc   = (const float*)d_in[12];
    const float* bc   = (const float*)d_in[13];
    const float* Wcls = (const float*)d_in[14];
    const float* bcls = (const float*)d_in[15];
    float* out = (float*)d_out;

    float *Ah, *Ac, *Bh, *Bc;
    cudaGetSymbolAddress((void**)&Ah, g_bufA_h);
    cudaGetSymbolAddress((void**)&Ac, g_bufA_c);
    cudaGetSymbolAddress((void**)&Bh, g_bufB_h);
    cudaGetSymbolAddress((void**)&Bc, g_bufB_c);

    cudaFuncSetAttribute(level_fused,  cudaFuncAttributeMaxDynamicSharedMemorySize, LV_SMEM);
    cudaFuncSetAttribute(leaf_fused,   cudaFuncAttributeMaxDynamicSharedMemorySize, LF_SMEM);
    cudaFuncSetAttribute(small_levels, cudaFuncAttributeMaxDynamicSharedMemorySize, SL_SMEM);

    pack_weights<<<256, 256>>>(Wp, Wfl, Wfr, Wi, Wo, Wc, bfl, bfr, bi, bo, bc);

    leaf_fused<<<dim3(NODES0 / 128, 2), 256, LF_SMEM>>>(leaf_ids, emb, bp, Ah, Ac);

    float *inH = Ah, *inC = Ac, *outH = Bh, *outC = Bc;
    int cur = NODES0;
    while (cur > 4096) {
        int Mout = cur >> 1;
        dim3 grid(Mout / 128, 8);
        level_fused<<<grid, 256, LV_SMEM>>>(inH, inC, outH, outC, Mout);
        float* t;
        t = inH; inH = outH; outH = t;
        t = inC; inC = outC; outC = t;
        cur = Mout;
    }

    small_levels<<<SL_GRID, 256, SL_SMEM>>>(inH, inC, outH, outC, Wcls, bcls, out);
}